// round 4
// baseline (speedup 1.0000x reference)
#include <cuda_runtime.h>

// Fast Hadamard Transform, DIM = 4096, fp32 — software-pipelined multi-row CTAs.
//
// Per row (same verified dataflow as R3):
//   Pass 1 (regs, FWHT-32): element bits {11,10,9,1,0}   (float4-coalesced loads)
//   one XOR-swizzled SMEM exchange (natural element order, conflict-free)
//   Pass 2 (regs, FWHT-32): element bits {8..4}
//   2 shuffle-FWHT stages:  element bits {3,2}           (lane bits 2,3)
//
// New: 256 threads = 2 rows per iteration, ITERS iterations per CTA, with the
// next iteration's global loads issued before this iteration's compute+store,
// keeping the HBM read stream continuously in flight.

#define FWHT_DIM 4096
#define THREADS 256
#define ROWS_PER_ITER 2
#define ITERS 4
#define ROWS_PER_CTA (ROWS_PER_ITER * ITERS)   // 8

// scale = 2^-(L(L+1)/4) with L=12 -> 2^-39
#define FWHT_SCALE 0x1p-39f

__device__ __forceinline__ void fwht32(float r[32]) {
#pragma unroll
    for (int h = 1; h < 32; h <<= 1) {
#pragma unroll
        for (int k = 0; k < 32; k++) {
            if (!(k & h)) {
                float a = r[k];
                float b = r[k ^ h];
                r[k]     = a + b;
                r[k ^ h] = a - b;
            }
        }
    }
}

// smem swizzle: phys = a ^ (bit9(a) << 4)  (XOR by 16 floats = 64B, keeps
// 16B alignment for float4 accesses)
__device__ __forceinline__ int swz(int a) { return a ^ (((a >> 9) & 1) << 4); }

__device__ __forceinline__ void load_row(float r[32], const float* __restrict__ xr,
                                         int t) {
#pragma unroll
    for (int k = 0; k < 8; k++) {
        float4 v = *reinterpret_cast<const float4*>(xr + k * 512 + t * 4);
        r[k * 4 + 0] = v.x;
        r[k * 4 + 1] = v.y;
        r[k * 4 + 2] = v.z;
        r[k * 4 + 3] = v.w;
    }
}

__global__ void __launch_bounds__(THREADS)
fwht4096_kernel(const float* __restrict__ x, float* __restrict__ out, int rows) {
    __shared__ float s[ROWS_PER_ITER * FWHT_DIM];   // 32 KB

    const int tid  = threadIdx.x;
    const int half = tid >> 7;       // which of the 2 rows this iteration
    const int t    = tid & 127;      // thread within row (= i[8:2] at load)
    const int lane = tid & 31;

    float* __restrict__ sr = s + half * FWHT_DIM;

    // Thread's fixed element coordinates for the pass-2 / store layout:
    // i[11:10] = t[6:5], i9 = lane4, i[3:0] = lane[3:0]; regs j' = i[8:4].
    const int base_idx = ((t >> 5) << 10) + ((t & 16) << 5) + (t & 15);

    // First row handled by this thread.
    long row = (long)blockIdx.x * ROWS_PER_CTA + half;

    float cur[32];
    bool active = (row < rows);
    if (active) load_row(cur, x + row * FWHT_DIM, t);

#pragma unroll
    for (int it = 0; it < ITERS; ++it) {
        // ---- Pass 1: element bits {11,10,9,1,0} ----
        fwht32(cur);

        // ---- SMEM write (natural order, swizzled; STS.128 conflict-free) ----
        if (active) {
#pragma unroll
            for (int k = 0; k < 8; k++) {
                int a = k * 512 + t * 4;
                *reinterpret_cast<float4*>(sr + swz(a)) =
                    make_float4(cur[k * 4 + 0], cur[k * 4 + 1],
                                cur[k * 4 + 2], cur[k * 4 + 3]);
            }
        }
        __syncthreads();

        // ---- SMEM read: regs j' = i[8:4] (bank-bijective, conflict-free) ----
        float v[32];
        if (active) {
#pragma unroll
            for (int j = 0; j < 32; j++) {
                v[j] = sr[swz(base_idx + j * 16)];
            }
        }

        // ---- Prefetch next iteration's row (hides DRAM latency under
        //      pass 2 + shuffles + stores) ----
        const long nrow = row + ROWS_PER_ITER;
        const bool nactive = (it + 1 < ITERS) && (nrow < rows);
        if (nactive) load_row(cur, x + nrow * FWHT_DIM, t);

        // ---- Pass 2: element bits {8..4} ----
        fwht32(v);

        // ---- Shuffle-FWHT over element bits {2,3} = lane bits {2,3} ----
        // (uniform per warp: all 32 lanes share `half`, hence `active`)
#pragma unroll
        for (int m = 4; m <= 8; m <<= 1) {
            const bool hi = (lane & m) != 0;
#pragma unroll
            for (int j = 0; j < 32; j++) {
                float p = __shfl_xor_sync(0xffffffffu, v[j], m, 32);
                v[j] = hi ? (p - v[j]) : (v[j] + p);
            }
        }

        // ---- Scale + store (two full 64B-sector runs per STG inst) ----
        if (active) {
            float* __restrict__ yw = out + row * FWHT_DIM + base_idx;
#pragma unroll
            for (int j = 0; j < 32; j++) {
                yw[j * 16] = v[j] * FWHT_SCALE;
            }
        }

        row = nrow;
        active = (row < rows);
        if (it + 1 < ITERS) __syncthreads();   // guard smem reuse
    }
}

extern "C" void kernel_launch(void* const* d_in, const int* in_sizes, int n_in,
                              void* d_out, int out_size) {
    const float* x = (const float*)d_in[0];
    float* out = (float*)d_out;
    const int rows = in_sizes[0] / FWHT_DIM;   // 8192
    const int grid = (rows + ROWS_PER_CTA - 1) / ROWS_PER_CTA;   // 1024
    fwht4096_kernel<<<grid, THREADS>>>(x, out, rows);
}

// round 5
// speedup vs baseline: 1.0860x; 1.0860x over previous
#include <cuda_runtime.h>

// Fast Hadamard Transform, DIM = 4096, fp32.
// 128 threads per row; cp.async-staged double-buffered pipeline, 8 rows/CTA.
//
// Per row:
//   cp.async.cg  global -> smem buf (natural element order, XOR-swizzled)
//   LDS  pass-1 inputs (float4, conflict-free)  -> FWHT-32 over bits {11,10,9,1,0}
//   STS  results in place (same addresses)
//   LDS  pass-2 inputs (bank-bijective)         -> FWHT-32 over bits {8..4}
//   2 shuffle-FWHT stages over bits {3,2} (lane bits 2,3)
//   streaming stores (__stcs) — output is write-once; keep input resident in L2.

#define FWHT_DIM 4096
#define THREADS 128
#define ROWS_PER_CTA 8

// scale = 2^-(L(L+1)/4) with L=12 -> 2^-39
#define FWHT_SCALE 0x1p-39f

__device__ __forceinline__ void fwht32(float r[32]) {
#pragma unroll
    for (int h = 1; h < 32; h <<= 1) {
#pragma unroll
        for (int k = 0; k < 32; k++) {
            if (!(k & h)) {
                float a = r[k];
                float b = r[k ^ h];
                r[k]     = a + b;
                r[k ^ h] = a - b;
            }
        }
    }
}

// smem swizzle: phys = a ^ (bit9(a) << 4) — XOR by 16 floats (64B), keeps
// 16B alignment for float4 / cp.async-16B accesses.
__device__ __forceinline__ int swz(int a) { return a ^ (((a >> 9) & 1) << 4); }

__device__ __forceinline__ unsigned smem_u32(const void* p) {
    return (unsigned)__cvta_generic_to_shared(p);
}

// Prefetch one row (16KB) into a smem buffer: 8 x cp.async.cg 16B per thread.
__device__ __forceinline__ void prefetch_row(float* buf, const float* __restrict__ xr,
                                             int t, bool active) {
    if (active) {
#pragma unroll
        for (int k = 0; k < 8; k++) {
            int a = k * 512 + t * 4;                    // float index, 16B-aligned
            unsigned dst = smem_u32(buf + swz(a));
            const float* src = xr + a;
            asm volatile("cp.async.cg.shared.global [%0], [%1], 16;\n"
                         :: "r"(dst), "l"(src));
        }
    }
    asm volatile("cp.async.commit_group;\n");
}

__global__ void __launch_bounds__(THREADS)
fwht4096_kernel(const float* __restrict__ x, float* __restrict__ out, int rows) {
    __shared__ float s[2][FWHT_DIM];   // 32 KB double buffer

    const int t    = threadIdx.x;      // 0..127
    const int lane = t & 31;

    // Pass-2 / store layout: i[11:10]=t[6:5], i9=lane4, i[3:0]=lane[3:0];
    // regs j' = i[8:4]; shuffle handles i[3:2] (lane bits 3,2).
    const int base_idx = ((t >> 5) << 10) + ((t & 16) << 5) + (t & 15);

    const long row0 = (long)blockIdx.x * ROWS_PER_CTA;

    // Prologue: stage rows 0 and 1.
    prefetch_row(s[0], x + (row0 + 0) * FWHT_DIM, t, row0 + 0 < rows);
    prefetch_row(s[1], x + (row0 + 1) * FWHT_DIM, t, row0 + 1 < rows);

#pragma unroll 1
    for (int it = 0; it < ROWS_PER_CTA; ++it) {
        const long row = row0 + it;
        float* buf = s[it & 1];

        // Wait for this row's staging (allow 1 younger group in flight).
        asm volatile("cp.async.wait_group 1;\n" ::: "memory");
        __syncthreads();

        if (row < rows) {
            float r[32];

            // ---- Pass 1 inputs: r[k*4+q] = elem (k<<9)|(t<<2)|q ----
            // 8 x LDS.128, lane-consecutive 16B -> conflict-free.
#pragma unroll
            for (int k = 0; k < 8; k++) {
                float4 v = *reinterpret_cast<const float4*>(buf + swz(k * 512 + t * 4));
                r[k * 4 + 0] = v.x;
                r[k * 4 + 1] = v.y;
                r[k * 4 + 2] = v.z;
                r[k * 4 + 3] = v.w;
            }
            fwht32(r);   // element bits {11,10,9,1,0}

            __syncthreads();   // all reads done before in-place overwrite

            // ---- In-place exchange: write results to the SAME addresses ----
#pragma unroll
            for (int k = 0; k < 8; k++) {
                *reinterpret_cast<float4*>(buf + swz(k * 512 + t * 4)) =
                    make_float4(r[k * 4 + 0], r[k * 4 + 1], r[k * 4 + 2], r[k * 4 + 3]);
            }
            __syncthreads();

            // ---- Pass 2 inputs: regs j' = i[8:4] (bank-bijective) ----
            float v[32];
#pragma unroll
            for (int j = 0; j < 32; j++) {
                v[j] = buf[swz(base_idx + j * 16)];
            }
            __syncthreads();   // reads done before cp.async refill of buf

            // ---- Refill this buffer with row it+2 ----
            prefetch_row(buf, x + (row + 2) * FWHT_DIM, t,
                         (it + 2 < ROWS_PER_CTA) && (row + 2 < rows));

            // ---- Pass 2: element bits {8..4} ----
            fwht32(v);

            // ---- Shuffle-FWHT over element bits {2,3} = lane bits {2,3} ----
#pragma unroll
            for (int m = 4; m <= 8; m <<= 1) {
                const bool hi = (lane & m) != 0;
#pragma unroll
                for (int j = 0; j < 32; j++) {
                    float p = __shfl_xor_sync(0xffffffffu, v[j], m, 32);
                    v[j] = hi ? (p - v[j]) : (v[j] + p);
                }
            }

            // ---- Scale + streaming store (write-once data: evict-first) ----
            float* __restrict__ yw = out + row * FWHT_DIM + base_idx;
#pragma unroll
            for (int j = 0; j < 32; j++) {
                __stcs(yw + j * 16, v[j] * FWHT_SCALE);
            }
        } else {
            // Keep group accounting and barriers uniform for inactive tail.
            __syncthreads();
            __syncthreads();
            __syncthreads();
            prefetch_row(buf, x, t, false);
        }
    }
}

extern "C" void kernel_launch(void* const* d_in, const int* in_sizes, int n_in,
                              void* d_out, int out_size) {
    const float* x = (const float*)d_in[0];
    float* out = (float*)d_out;
    const int rows = in_sizes[0] / FWHT_DIM;                 // 8192
    const int grid = (rows + ROWS_PER_CTA - 1) / ROWS_PER_CTA;  // 1024
    fwht4096_kernel<<<grid, THREADS>>>(x, out, rows);
}